// round 1
// baseline (speedup 1.0000x reference)
#include <cuda_runtime.h>
#include <cstdint>

// SpikeFP64ScaleBy2K — soft-logic FP64 scale-by-2^k collapsed to integer bit ops.
// Layout: rows of 64 float "bits" (0.0/1.0). Warp-per-row: lane j holds bits
// {2j, 2j+1} via one coalesced float2 load; __ballot_sync packs the row into
// even/odd 32-bit masks; Morton interleave + brev recover the fields.

static constexpr int ROWS_PER_WARP = 4;
static constexpr int WARPS_PER_BLOCK = 8;
static constexpr int BLOCK_THREADS = WARPS_PER_BLOCK * 32;

__device__ __forceinline__ unsigned part1by1(unsigned n) {
    // spread low 16 bits to even positions
    n &= 0x0000FFFFu;
    n = (n | (n << 8)) & 0x00FF00FFu;
    n = (n | (n << 4)) & 0x0F0F0F0Fu;
    n = (n | (n << 2)) & 0x33333333u;
    n = (n | (n << 1)) & 0x55555555u;
    return n;
}

__global__ void __launch_bounds__(BLOCK_THREADS)
scale2k_kernel(const float2* __restrict__ x2,
               const float2* __restrict__ k2,
               float2* __restrict__ o2,
               int nrows)
{
    const int lane = threadIdx.x & 31;
    const int warp = blockIdx.x * WARPS_PER_BLOCK + (threadIdx.x >> 5);
    const int row0 = warp * ROWS_PER_WARP;
    if (row0 >= nrows) return;  // warp-uniform exit

    // Front-batch all loads: 8 independent LDG.64 per lane (MLP for DRAM latency)
    float2 xv[ROWS_PER_WARP];
    float2 kv[ROWS_PER_WARP];
#pragma unroll
    for (int r = 0; r < ROWS_PER_WARP; ++r) {
        if (row0 + r < nrows) {  // warp-uniform
            long idx = (long)(row0 + r) * 32 + lane;
            xv[r] = __ldg(&x2[idx]);
            kv[r] = __ldg(&k2[idx]);
        }
    }

#pragma unroll
    for (int r = 0; r < ROWS_PER_WARP; ++r) {
        if (row0 + r >= nrows) break;  // warp-uniform

        // Pack row bits: bit j of be* = array[2j], bit j of bo* = array[2j+1]
        unsigned bex = __ballot_sync(0xFFFFFFFFu, xv[r].x != 0.0f);
        unsigned box = __ballot_sync(0xFFFFFFFFu, xv[r].y != 0.0f);
        unsigned bek = __ballot_sync(0xFFFFFFFFu, kv[r].x != 0.0f);
        unsigned bok = __ballot_sync(0xFFFFFFFFu, kv[r].y != 0.0f);

        // kb bit p = k[p] for p in 0..31 (all we need: sign, exp, top-15 mantissa)
        unsigned kb   = part1by1(bek) | (part1by1(bok) << 1);
        unsigned revk = __brev(kb);

        // e_k (biased, 11-bit): k[1]..k[11] MSB-first
        unsigned e_k = (revk >> 20) & 0x7FFu;
        // val = 1.m (implicit 1 + top 15 mantissa bits), 16-bit
        unsigned val = 0x8000u | ((revk >> 5) & 0x7FFFu);
        // shift = (e_k + 1025) & 0x7FF;  t = 15 - (shift & 15)
        unsigned t = (~(e_k + 1025u)) & 15u;
        unsigned k_abs = (val >> t) & 0x7FFu;
        // two's-complement negate if sign of k set
        unsigned k_final = (kb & 1u) ? ((0u - k_abs) & 0x7FFu) : k_abs;

        // e_x from x's bits 1..11
        unsigned xb  = part1by1(bex) | (part1by1(box) << 1);
        unsigned e_x = (__brev(xb) >> 20) & 0x7FFu;
        unsigned e_new = (e_x + k_final) & 0x7FFu;

        // k_is_zero over k[1..63]: exclude even-mask bit 0 (sign bit)
        bool nz = ((bek & ~1u) | bok) != 0u;

        float2 ov = xv[r];
        if (nz && lane <= 5) {
            // output position 2j (j=1..5) <- e_new bit (11-2j)
            if (lane >= 1) ov.x = (float)((e_new >> (11 - 2 * lane)) & 1u);
            // output position 2j+1 (j=0..5) <- e_new bit (10-2j)
            ov.y = (float)((e_new >> (10 - 2 * lane)) & 1u);
        }

        long idx = (long)(row0 + r) * 32 + lane;
        o2[idx] = ov;
    }
}

extern "C" void kernel_launch(void* const* d_in, const int* in_sizes, int n_in,
                              void* d_out, int out_size) {
    const float2* x2 = (const float2*)d_in[0];
    const float2* k2 = (const float2*)d_in[1];
    float2* o2 = (float2*)d_out;

    const int nrows = in_sizes[0] / 64;
    const int nwarps = (nrows + ROWS_PER_WARP - 1) / ROWS_PER_WARP;
    const int nblocks = (nwarps + WARPS_PER_BLOCK - 1) / WARPS_PER_BLOCK;

    scale2k_kernel<<<nblocks, BLOCK_THREADS>>>(x2, k2, o2, nrows);
}

// round 2
// speedup vs baseline: 1.2029x; 1.2029x over previous
#include <cuda_runtime.h>
#include <cstdint>

// SpikeFP64ScaleBy2K — soft-logic FP64 scale-by-2^k collapsed to integer bit ops.
// R2: replace ballot+Morton decode (ALU-bound, 84% pipe) with 2x REDUX.ADD per
// row using per-lane packed weights. Same verified bit logic as R1 (rel_err 0).
//
// Row layout: 64 floats (0.0/1.0), MSB-first IEEE-754 double bit pattern.
// Lane j holds bits {2j, 2j+1} via one coalesced float2 load.
//
// Packed reduction words:
//   r1 = sum of per-lane ((e_k_weight << 16) | val_weight) over k bits
//        -> e_k = r1>>16 (<=0x7FF), val_frac = r1&0xFFFF (<=0x7FFF)
//   r2 = sum of per-lane (e_x_weight | nz_contrib<<12 | sign<<20)
//        -> e_x = r2&0x7FF, nz = (r2>>12)&0xFF != 0, s_k = r2>>20

static constexpr int ROWS_PER_WARP = 4;
static constexpr int WARPS_PER_BLOCK = 8;
static constexpr int BLOCK_THREADS = WARPS_PER_BLOCK * 32;

__global__ void __launch_bounds__(BLOCK_THREADS)
scale2k_kernel(const float2* __restrict__ x2,
               const float2* __restrict__ k2,
               float2* __restrict__ o2,
               int nrows)
{
    const int lane = threadIdx.x & 31;
    const int warp = blockIdx.x * WARPS_PER_BLOCK + (threadIdx.x >> 5);
    const int row0 = warp * ROWS_PER_WARP;
    if (row0 >= nrows) return;  // warp-uniform exit

    // ---- per-lane weights (computed once, hoisted out of the row loop) ----
    // e_k / e_x weights: bit position p in 1..11, weight 2^(11-p)
    //   x-part: p = 2*lane  (lanes 1..5):  2^(11-2*lane)
    //   y-part: p = 2*lane+1 (lanes 0..5): 2^(10-2*lane)
    const unsigned wE_x = (lane >= 1 && lane <= 5) ? (1u << (11 - 2 * lane)) : 0u;
    const unsigned wE_y = (lane <= 5) ? (1u << (10 - 2 * lane)) : 0u;
    // val (top-15 mantissa) weights: p in 12..26, weight 2^(26-p)
    //   x-part: lanes 6..13: 2^(26-2*lane);  y-part: lanes 6..12: 2^(25-2*lane)
    const unsigned wV_x = (lane >= 6 && lane <= 13) ? (1u << (26 - 2 * lane)) : 0u;
    const unsigned wV_y = (lane >= 6 && lane <= 12) ? (1u << (25 - 2 * lane)) : 0u;
    // combined k-word weights
    const unsigned w1x = (wE_x << 16) | wV_x;
    const unsigned w1y = (wE_y << 16) | wV_y;
    // x/flags word: k even bit -> sign (lane 0 = k[0]) or nz-count; k odd bit -> nz-count
    const unsigned w2kx = (lane == 0) ? (1u << 20) : (1u << 12);
    const unsigned w2ky = 1u << 12;
    // patch shift amounts (meaningful only for lanes 0..5)
    const unsigned sh_x = (unsigned)(11 - 2 * lane) & 31u;
    const unsigned sh_y = (unsigned)(10 - 2 * lane) & 31u;
    const bool lane_le5 = (lane <= 5);
    const bool lane_ge1 = (lane >= 1);

    // ---- front-batch loads: 8 independent LDG.64 per lane (MLP) ----
    float2 xv[ROWS_PER_WARP];
    float2 kv[ROWS_PER_WARP];
#pragma unroll
    for (int r = 0; r < ROWS_PER_WARP; ++r) {
        if (row0 + r < nrows) {  // warp-uniform
            long idx = (long)(row0 + r) * 32 + lane;
            xv[r] = __ldg(&x2[idx]);
            kv[r] = __ldg(&k2[idx]);
        }
    }

#pragma unroll
    for (int r = 0; r < ROWS_PER_WARP; ++r) {
        if (row0 + r >= nrows) break;  // warp-uniform

        const bool kx = (kv[r].x != 0.0f);
        const bool ky = (kv[r].y != 0.0f);
        const bool xx = (xv[r].x != 0.0f);
        const bool xy = (xv[r].y != 0.0f);

        unsigned c1 = (kx ? w1x : 0u) + (ky ? w1y : 0u);
        unsigned c2 = (xx ? wE_x : 0u) + (xy ? wE_y : 0u)
                    + (kx ? w2kx : 0u) + (ky ? w2ky : 0u);

        unsigned r1 = __reduce_add_sync(0xFFFFFFFFu, c1);
        unsigned r2 = __reduce_add_sync(0xFFFFFFFFu, c2);

        // ---- uniform scalar chain (verified in R1) ----
        unsigned e_k = r1 >> 16;
        unsigned val = 0x8000u | (r1 & 0xFFFFu);
        unsigned t = (~(e_k + 1025u)) & 15u;
        unsigned k_abs = (val >> t) & 0x7FFu;
        unsigned s_k = (r2 >> 20) & 1u;
        unsigned k_final = s_k ? ((0u - k_abs) & 0x7FFu) : k_abs;
        unsigned e_x = r2 & 0x7FFu;
        unsigned e_new = (e_x + k_final) & 0x7FFu;
        bool nz = ((r2 >> 12) & 0xFFu) != 0u;

        // ---- patch exponent field (bits 1..11 -> lanes 0..5) ----
        float2 ov = xv[r];
        if (nz && lane_le5) {
            if (lane_ge1) ov.x = (float)((e_new >> sh_x) & 1u);
            ov.y = (float)((e_new >> sh_y) & 1u);
        }

        long idx = (long)(row0 + r) * 32 + lane;
        o2[idx] = ov;
    }
}

extern "C" void kernel_launch(void* const* d_in, const int* in_sizes, int n_in,
                              void* d_out, int out_size) {
    const float2* x2 = (const float2*)d_in[0];
    const float2* k2 = (const float2*)d_in[1];
    float2* o2 = (float2*)d_out;

    const int nrows = in_sizes[0] / 64;
    const int nwarps = (nrows + ROWS_PER_WARP - 1) / ROWS_PER_WARP;
    const int nblocks = (nwarps + WARPS_PER_BLOCK - 1) / WARPS_PER_BLOCK;

    scale2k_kernel<<<nblocks, BLOCK_THREADS>>>(x2, k2, o2, nrows);
}